// round 15
// baseline (speedup 1.0000x reference)
#include <cuda_runtime.h>
#include <cuda_fp16.h>
#include <cstdint>
#include <math.h>

#define N_PTS 100000
#define KNB   16
#define CIN   128
#define COUT  256
#define NKP   15
#define CXJ   131            // CIN + 3
#define MROW  132            // per-m row: x 0..127, pj 128..130, pad 131
#define KP2   1984           // 15*132 = 1980, padded to 31*64
#define NCHUNK 31
#define PPB   8              // points per block; 100000 = 8*12500

#define XJ_STRIDE 136
#define XJ_ROWB   272
#define WARP_XJ   (16 * XJ_STRIDE)

// ---------------- scratch ----------------------------------------------------
__device__ __align__(128) __half g_agg[(size_t)N_PTS * KP2];
__device__ __align__(128) __half g_wbt[(size_t)KP2 * COUT];
__device__ __align__(128) __half g_x16[(size_t)N_PTS * CIN];

// ---------------- PTX helpers (sm_103 base target only) ---------------------
__device__ __forceinline__ uint32_t smem_u32(const void* p) {
    uint32_t a;
    asm("{ .reg .u64 t; cvta.to.shared.u64 t, %1; cvt.u32.u64 %0, t; }"
        : "=r"(a) : "l"(p));
    return a;
}

__device__ __forceinline__ void cp_async16(uint32_t dst, const void* src,
                                           uint32_t srcsize) {
    asm volatile("cp.async.cg.shared.global [%0], [%1], 16, %2;"
                 :: "r"(dst), "l"(src), "r"(srcsize) : "memory");
}

__device__ __forceinline__ void cp_commit() {
    asm volatile("cp.async.commit_group;" ::: "memory");
}

template <int N>
__device__ __forceinline__ void cp_wait() {
    asm volatile("cp.async.wait_group %0;" :: "n"(N) : "memory");
}

__device__ __forceinline__ void ldsm_x4(uint32_t* r, uint32_t addr) {
    asm volatile("ldmatrix.sync.aligned.m8n8.x4.shared.b16 {%0,%1,%2,%3}, [%4];"
                 : "=r"(r[0]), "=r"(r[1]), "=r"(r[2]), "=r"(r[3]) : "r"(addr));
}

__device__ __forceinline__ void ldsm_x4_t(uint32_t* r, uint32_t addr) {
    asm volatile("ldmatrix.sync.aligned.m8n8.x4.trans.shared.b16 {%0,%1,%2,%3}, [%4];"
                 : "=r"(r[0]), "=r"(r[1]), "=r"(r[2]), "=r"(r[3]) : "r"(addr));
}

__device__ __forceinline__ void ldsm_x2_t(uint32_t* r, uint32_t addr) {
    asm volatile("ldmatrix.sync.aligned.m8n8.x2.trans.shared.b16 {%0,%1}, [%2];"
                 : "=r"(r[0]), "=r"(r[1]) : "r"(addr));
}

__device__ __forceinline__ void mma_fp16(float* c, const uint32_t* a,
                                         const uint32_t* b) {
    asm volatile(
        "mma.sync.aligned.m16n8k16.row.col.f32.f16.f16.f32 "
        "{%0,%1,%2,%3}, {%4,%5,%6,%7}, {%8,%9}, {%0,%1,%2,%3};"
        : "+f"(c[0]), "+f"(c[1]), "+f"(c[2]), "+f"(c[3])
        : "r"(a[0]), "r"(a[1]), "r"(a[2]), "r"(a[3]), "r"(b[0]), "r"(b[1]));
}

// ---------------------------------------------------------------------------
// x -> fp16 (bit-identical path)
// ---------------------------------------------------------------------------
__global__ void xcvt_kernel(const float* __restrict__ x) {
    size_t t = (size_t)blockIdx.x * blockDim.x + threadIdx.x;
    if (t >= (size_t)N_PTS * CIN / 8) return;
    float4 v0 = ((const float4*)x)[2 * t + 0];
    float4 v1 = ((const float4*)x)[2 * t + 1];
    union { uint4 u; __half2 h[4]; } pk;
    pk.h[0] = __floats2half2_rn(v0.x, v0.y);
    pk.h[1] = __floats2half2_rn(v0.z, v0.w);
    pk.h[2] = __floats2half2_rn(v1.x, v1.y);
    pk.h[3] = __floats2half2_rn(v1.z, v1.w);
    ((uint4*)g_x16)[t] = pk.u;
}

// ---------------------------------------------------------------------------
// Weight prep (MROW layout)
// ---------------------------------------------------------------------------
__global__ void wt_split_kernel(const float* __restrict__ conv_w) {
    int e = blockIdx.x * blockDim.x + threadIdx.x;
    if (e >= KP2 * COUT) return;
    int col = e / COUT;
    int n   = e - col * COUT;
    float v = 0.0f;
    if (col < NKP * MROW) {
        int m  = col / MROW;
        int nc = col - m * MROW;
        if (nc != 131) {
            int c = (nc < 128) ? (nc + 3) : (nc - 128);
            v = conv_w[((size_t)n * CXJ + c) * NKP + m];
        }
    }
    g_wbt[e] = __float2half_rn(v);
}

// ---------------------------------------------------------------------------
// Preprocess (R11 verbatim): warp-per-point tensor-core mini-GEMM, fp16 gather
// ---------------------------------------------------------------------------
__global__ __launch_bounds__(256) void preprocess_kernel(
    const float* __restrict__ p,
    const float* __restrict__ kp,
    const int*   __restrict__ idx)
{
    __shared__ __align__(16) __half s_xj[PPB][WARP_XJ];

    const int wid  = threadIdx.x >> 5;
    const int lane = threadIdx.x & 31;
    const int n    = blockIdx.x * PPB + wid;

    __half* xj = &s_xj[wid][0];
    const uint32_t xj_b = smem_u32(xj);

    int idxv = 0;
    if (lane < KNB) idxv = idx[(size_t)n * KNB + lane];

    const float px = p[3 * n + 0];
    const float py = p[3 * n + 1];
    const float pz = p[3 * n + 2];

    float dx = 0.f, dy = 0.f, dz = 0.f, l2 = 0.f;
    if (lane < KNB) {
        dx = p[3 * idxv + 0] - px;
        dy = p[3 * idxv + 1] - py;
        dz = p[3 * idxv + 2] - pz;
        l2 = sqrtf(dx * dx + dy * dy + dz * dz);
    }
    float mx = l2;
    #pragma unroll
    for (int o = 8; o >= 1; o >>= 1)
        mx = fmaxf(mx, __shfl_xor_sync(0xFFFFFFFFu, mx, o));
    const float inv = 1.0f / (mx + 1e-10f);
    const float pjx = dx * inv, pjy = dy * inv, pjz = dz * inv;

    #pragma unroll
    for (int i = 0; i < 8; i++) {
        int v   = lane + 32 * i;
        int row = v >> 4;
        int seg = v & 15;
        int j = __shfl_sync(0xFFFFFFFFu, idxv, row);
        uint4 d = *(const uint4*)(g_x16 + (size_t)j * CIN + 8 * seg);
        *(uint4*)(xj + row * XJ_STRIDE + 8 * seg) = d;
    }
    if (lane < KNB) {
        union { uint4 u; __half h[8]; } pk;
        pk.u = make_uint4(0u, 0u, 0u, 0u);
        pk.h[0] = __float2half_rn(pjx);
        pk.h[1] = __float2half_rn(pjy);
        pk.h[2] = __float2half_rn(pjz);
        *(uint4*)(xj + lane * XJ_STRIDE + 128) = pk.u;
    }
    __syncwarp();

    const int q  = lane & 3;
    const int r  = lane >> 2;
    const int k0 = 2 * q;
    const int kl[4] = { k0, k0 + 1, k0 + 8, k0 + 9 };
    float pax[4], pay[4], paz[4];
    #pragma unroll
    for (int i = 0; i < 4; i++) {
        pax[i] = __shfl_sync(0xFFFFFFFFu, pjx, kl[i]);
        pay[i] = __shfl_sync(0xFFFFFFFFu, pjy, kl[i]);
        paz[i] = __shfl_sync(0xFFFFFFFFu, pjz, kl[i]);
    }
    const float INV_SCALE = (float)(1.0 / (0.3 * 0.3 * 2.0 + 1e-10));
    const bool  mhi_ok = (r + 8) < NKP;
    const int   mh = mhi_ok ? (r + 8) : 0;
    const float klx = kp[3 * r + 0], kly = kp[3 * r + 1], klz = kp[3 * r + 2];
    const float khx = kp[3 * mh + 0], khy = kp[3 * mh + 1], khz = kp[3 * mh + 2];

    float clo[4], chi[4];
    #pragma unroll
    for (int i = 0; i < 4; i++) {
        float ax = klx - pax[i], ay = kly - pay[i], az = klz - paz[i];
        clo[i] = __expf(-(ax * ax + ay * ay + az * az) * INV_SCALE);
        float bx = khx - pax[i], by = khy - pay[i], bz = khz - paz[i];
        chi[i] = mhi_ok ? __expf(-(bx * bx + by * by + bz * bz) * INV_SCALE) : 0.f;
    }
    uint32_t afr[4];
    { union { uint32_t u; __half2 h; } t;
      t.h = __floats2half2_rn(clo[0], clo[1]); afr[0] = t.u;
      t.h = __floats2half2_rn(chi[0], chi[1]); afr[1] = t.u;
      t.h = __floats2half2_rn(clo[2], clo[3]); afr[2] = t.u;
      t.h = __floats2half2_rn(chi[2], chi[3]); afr[3] = t.u; }

    float acc[17][4];
    #pragma unroll
    for (int t = 0; t < 17; t++)
        #pragma unroll
        for (int i = 0; i < 4; i++) acc[t][i] = 0.f;

    const uint32_t b_row = xj_b + (uint32_t)(lane & 15) * XJ_ROWB +
                           (uint32_t)(lane >> 4) * 16u;
    #pragma unroll
    for (int nb = 0; nb < 8; nb++) {
        uint32_t t4[4];
        ldsm_x4_t(t4, b_row + (uint32_t)nb * 32u);
        mma_fp16(acc[2 * nb + 0], afr, &t4[0]);
        mma_fp16(acc[2 * nb + 1], afr, &t4[2]);
    }
    {
        uint32_t t2[2];
        ldsm_x2_t(t2, xj_b + (uint32_t)(lane & 15) * XJ_ROWB + 256u);
        mma_fp16(acc[16], afr, t2);
    }
    __syncwarp();

    __half* stg = xj;
    #pragma unroll
    for (int t = 0; t < 17; t++) {
        int c = 8 * t + 2 * q;
        if (t < 16 || q < 2) {
            union { uint32_t u; __half2 h; } v;
            v.h = __floats2half2_rn(acc[t][0], acc[t][1]);
            *(uint32_t*)(stg + r * MROW + c) = v.u;
            if (mhi_ok) {
                v.h = __floats2half2_rn(acc[t][2], acc[t][3]);
                *(uint32_t*)(stg + (r + 8) * MROW + c) = v.u;
            }
        }
    }
    if (lane == 0) *(uint2*)(stg + 1980) = make_uint2(0u, 0u);
    __syncwarp();

    __half* dst = g_agg + (size_t)n * KP2;
    #pragma unroll
    for (int i = lane; i < KP2 / 8; i += 32)
        *(uint4*)(dst + 8 * i) = *(const uint4*)(stg + 8 * i);
}

// ---------------------------------------------------------------------------
// GEMM v5: 128x128 tile, 16 warps (512 thr, warp tile 32x32), 2 CTAs/SM,
// 3-stage cp.async. n on fast grid axis (L2 A-pairing, kept from R14).
// ---------------------------------------------------------------------------
#define N_TILE   128
#define A_STRIDE 144u
#define B_STRIDE 272u
#define BOFF     18432u
#define STG      35840u
#define NSTAGE   3
#define SMEM_DYN (3u * STG)

__global__ __launch_bounds__(512, 2) void gemm_mma_kernel(
    const float* __restrict__ conv_b,
    const float* __restrict__ bn_gamma,
    const float* __restrict__ bn_beta,
    const float* __restrict__ bn_mean,
    const float* __restrict__ bn_var,
    float* __restrict__ out)
{
    extern __shared__ __align__(1024) char smem[];
    __shared__ __align__(16) float s_sc[N_TILE];
    __shared__ __align__(16) float s_bi[N_TILE];

    const uint32_t sb   = smem_u32(smem);
    const int tid    = threadIdx.x;
    const int wid    = tid >> 5;
    const int lane   = tid & 31;
    const int warp_m = wid >> 2;          // 0..3
    const int warp_n = wid & 3;           // 0..3
    const int m0     = blockIdx.y * 128;      // m slow
    const int n0     = blockIdx.x * N_TILE;   // n fast (L2 pairing)

    if (tid < N_TILE) {
        int col = n0 + tid;
        float s = bn_gamma[col] * rsqrtf(bn_var[col] + 1e-5f);
        s_sc[tid] = s;
        s_bi[tid] = (conv_b[col] - bn_mean[col]) * s + bn_beta[col];
    }

    float acc[2][4][4];
    #pragma unroll
    for (int i = 0; i < 2; i++)
        #pragma unroll
        for (int j = 0; j < 4; j++)
            #pragma unroll
            for (int qq = 0; qq < 4; qq++) acc[i][j][qq] = 0.0f;

    auto load_chunk = [&](int c, int stage) {
        const uint32_t base = sb + (uint32_t)stage * STG;
        // A: 128 rows x 8 segs (16B) = 1024 txns over 512 threads
        #pragma unroll
        for (int L = 0; L < 2; L++) {
            int v   = tid + L * 512;
            int row = v >> 3;
            int seg = v & 7;
            int gr  = m0 + row;
            uint32_t ok = (gr < N_PTS) ? 16u : 0u;
            int grc = (gr < N_PTS) ? gr : 0;
            const __half* src = g_agg + (size_t)grc * KP2 + (size_t)c * 64 + seg * 8;
            uint32_t dst = base + (uint32_t)row * A_STRIDE + (uint32_t)seg * 16u;
            cp_async16(dst, src, ok);
        }
        // B: 64 rows x 16 segs = 1024 txns
        #pragma unroll
        for (int L = 0; L < 2; L++) {
            int v    = tid + L * 512;
            int krow = v >> 4;
            int seg  = v & 15;
            const __half* src = g_wbt + (size_t)(c * 64 + krow) * COUT + n0 + seg * 8;
            uint32_t dst = base + BOFF +
                           (uint32_t)krow * B_STRIDE + (uint32_t)seg * 16u;
            cp_async16(dst, src, 16u);
        }
        cp_commit();
    };

    const uint32_t a_base = (uint32_t)(warp_m * 32 + (lane & 15)) * A_STRIDE +
                            (uint32_t)(lane >> 4) * 16u;
    const uint32_t b_base = (uint32_t)(lane & 15) * B_STRIDE + BOFF +
                            (uint32_t)(warp_n * 32 + (lane >> 4) * 8) * 2u;

    load_chunk(0, 0);
    load_chunk(1, 1);

    for (int c = 0; c < NCHUNK; c++) {
        if (c + 2 < NCHUNK) load_chunk(c + 2, (c + 2) % NSTAGE);
        else                cp_commit();
        cp_wait<2>();
        __syncthreads();

        const uint32_t stg = sb + (uint32_t)(c % NSTAGE) * STG;

        #pragma unroll
        for (int ks = 0; ks < 4; ks++) {
            uint32_t ah[2][4];
            #pragma unroll
            for (int mi = 0; mi < 2; mi++) {
                uint32_t aa = stg + a_base + (uint32_t)(mi * 16) * A_STRIDE +
                              (uint32_t)ks * 32u;
                ldsm_x4(ah[mi], aa);
            }
            uint32_t bh[4][2];
            #pragma unroll
            for (int nb = 0; nb < 2; nb++) {
                uint32_t ba = stg + b_base + (uint32_t)(ks * 16) * B_STRIDE +
                              (uint32_t)nb * 32u;
                uint32_t t[4];
                ldsm_x4_t(t, ba);
                bh[2*nb][0] = t[0]; bh[2*nb][1] = t[1];
                bh[2*nb+1][0] = t[2]; bh[2*nb+1][1] = t[3];
            }
            #pragma unroll
            for (int mi = 0; mi < 2; mi++)
                #pragma unroll
                for (int ni = 0; ni < 4; ni++)
                    mma_fp16(acc[mi][ni], ah[mi], bh[ni]);
        }
        __syncthreads();
    }

    // ---- epilogue: bias + BN + ReLU, float2 stores ----
    const int r_base = m0 + warp_m * 32;
    #pragma unroll
    for (int mi = 0; mi < 2; mi++) {
        #pragma unroll
        for (int h = 0; h < 2; h++) {
            int row = r_base + mi * 16 + (lane >> 2) + h * 8;
            if (row < N_PTS) {
                float* op = out + (size_t)row * COUT + n0;
                #pragma unroll
                for (int ni = 0; ni < 4; ni++) {
                    int lc = warp_n * 32 + ni * 8 + (lane & 3) * 2;
                    float2 v;
                    v.x = fmaxf(fmaf(acc[mi][ni][h*2+0], s_sc[lc],   s_bi[lc]),   0.0f);
                    v.y = fmaxf(fmaf(acc[mi][ni][h*2+1], s_sc[lc+1], s_bi[lc+1]), 0.0f);
                    *(float2*)(op + lc) = v;
                }
            }
        }
    }
}

// ---------------------------------------------------------------------------
extern "C" void kernel_launch(void* const* d_in, const int* in_sizes, int n_in,
                              void* d_out, int out_size) {
    const float* p     = (const float*)d_in[0];
    const float* x     = (const float*)d_in[1];
    const float* kp    = (const float*)d_in[2];
    const float* w     = (const float*)d_in[3];
    const float* b     = (const float*)d_in[4];
    const float* gamma = (const float*)d_in[5];
    const float* beta  = (const float*)d_in[6];
    const float* mean  = (const float*)d_in[7];
    const float* var   = (const float*)d_in[8];
    const int*   idx   = (const int*)d_in[9];
    float* out = (float*)d_out;

    cudaFuncSetAttribute(gemm_mma_kernel,
                         cudaFuncAttributeMaxDynamicSharedMemorySize, SMEM_DYN);

    xcvt_kernel<<<(N_PTS * CIN / 8 + 255) / 256, 256>>>(x);
    wt_split_kernel<<<(KP2 * COUT + 255) / 256, 256>>>(w);
    preprocess_kernel<<<N_PTS / PPB, 256>>>(p, kp, idx);
    dim3 grid(COUT / N_TILE, (N_PTS + 127) / 128);   // n fast, m slow
    gemm_mma_kernel<<<grid, 512, SMEM_DYN>>>(b, gamma, beta, mean, var, out);
}

// round 16
// speedup vs baseline: 1.0520x; 1.0520x over previous
#include <cuda_runtime.h>
#include <cuda_fp16.h>
#include <cstdint>
#include <math.h>

#define N_PTS 100000
#define KNB   16
#define CIN   128
#define COUT  256
#define NKP   15
#define CXJ   131            // CIN + 3
#define MROW  132            // per-m row: x 0..127, pj 128..130, pad 131
#define KP2   1984           // 15*132 = 1980, padded to 31*64
#define NCHUNK 31
#define PPB   8              // points per block; 100000 = 8*12500

#define XJ_STRIDE 136
#define XJ_ROWB   272
#define WARP_XJ   (16 * XJ_STRIDE)

// ---------------- scratch ----------------------------------------------------
__device__ __align__(128) __half g_agg[(size_t)N_PTS * KP2];
__device__ __align__(128) __half g_wbt[(size_t)KP2 * COUT];
__device__ __align__(128) __half g_x16[(size_t)N_PTS * CIN];

// ---------------- PTX helpers (sm_103 base target only) ---------------------
__device__ __forceinline__ uint32_t smem_u32(const void* p) {
    uint32_t a;
    asm("{ .reg .u64 t; cvta.to.shared.u64 t, %1; cvt.u32.u64 %0, t; }"
        : "=r"(a) : "l"(p));
    return a;
}

__device__ __forceinline__ void cp_async16(uint32_t dst, const void* src,
                                           uint32_t srcsize) {
    asm volatile("cp.async.cg.shared.global [%0], [%1], 16, %2;"
                 :: "r"(dst), "l"(src), "r"(srcsize) : "memory");
}

__device__ __forceinline__ void cp_commit() {
    asm volatile("cp.async.commit_group;" ::: "memory");
}

template <int N>
__device__ __forceinline__ void cp_wait() {
    asm volatile("cp.async.wait_group %0;" :: "n"(N) : "memory");
}

__device__ __forceinline__ void ldsm_x4(uint32_t* r, uint32_t addr) {
    asm volatile("ldmatrix.sync.aligned.m8n8.x4.shared.b16 {%0,%1,%2,%3}, [%4];"
                 : "=r"(r[0]), "=r"(r[1]), "=r"(r[2]), "=r"(r[3]) : "r"(addr));
}

__device__ __forceinline__ void ldsm_x4_t(uint32_t* r, uint32_t addr) {
    asm volatile("ldmatrix.sync.aligned.m8n8.x4.trans.shared.b16 {%0,%1,%2,%3}, [%4];"
                 : "=r"(r[0]), "=r"(r[1]), "=r"(r[2]), "=r"(r[3]) : "r"(addr));
}

__device__ __forceinline__ void ldsm_x2_t(uint32_t* r, uint32_t addr) {
    asm volatile("ldmatrix.sync.aligned.m8n8.x2.trans.shared.b16 {%0,%1}, [%2];"
                 : "=r"(r[0]), "=r"(r[1]) : "r"(addr));
}

__device__ __forceinline__ void mma_fp16(float* c, const uint32_t* a,
                                         const uint32_t* b) {
    asm volatile(
        "mma.sync.aligned.m16n8k16.row.col.f32.f16.f16.f32 "
        "{%0,%1,%2,%3}, {%4,%5,%6,%7}, {%8,%9}, {%0,%1,%2,%3};"
        : "+f"(c[0]), "+f"(c[1]), "+f"(c[2]), "+f"(c[3])
        : "r"(a[0]), "r"(a[1]), "r"(a[2]), "r"(a[3]), "r"(b[0]), "r"(b[1]));
}

// ---------------------------------------------------------------------------
// Merged prep: x -> fp16 copy  AND  weight transpose/convert (one launch).
// Both paths identical math to R14 -> bit-identical results.
// ---------------------------------------------------------------------------
#define XCVT_UNITS (N_PTS * CIN / 8)          // 1,600,000
#define WT_UNITS   (KP2 * COUT)               // 507,904
#define PREP_UNITS (XCVT_UNITS + WT_UNITS)

__global__ void prep_kernel(const float* __restrict__ x,
                            const float* __restrict__ conv_w) {
    int t = blockIdx.x * blockDim.x + threadIdx.x;
    if (t < XCVT_UNITS) {
        float4 v0 = ((const float4*)x)[2 * (size_t)t + 0];
        float4 v1 = ((const float4*)x)[2 * (size_t)t + 1];
        union { uint4 u; __half2 h[4]; } pk;
        pk.h[0] = __floats2half2_rn(v0.x, v0.y);
        pk.h[1] = __floats2half2_rn(v0.z, v0.w);
        pk.h[2] = __floats2half2_rn(v1.x, v1.y);
        pk.h[3] = __floats2half2_rn(v1.z, v1.w);
        ((uint4*)g_x16)[t] = pk.u;
    } else {
        int e = t - XCVT_UNITS;
        if (e >= WT_UNITS) return;
        int col = e / COUT;
        int n   = e - col * COUT;
        float v = 0.0f;
        if (col < NKP * MROW) {
            int m  = col / MROW;
            int nc = col - m * MROW;
            if (nc != 131) {
                int c = (nc < 128) ? (nc + 3) : (nc - 128);
                v = conv_w[((size_t)n * CXJ + c) * NKP + m];
            }
        }
        g_wbt[e] = __float2half_rn(v);
    }
}

// ---------------------------------------------------------------------------
// Preprocess v6: warp-per-point tensor-core mini-GEMM.
// x-gather issued as cp.async FIRST, overlapped with pj/corr/expf, waited
// just before the ldsm consumers. Same bytes/converts as R14 -> bit-identical.
// ---------------------------------------------------------------------------
__global__ __launch_bounds__(256) void preprocess_kernel(
    const float* __restrict__ p,
    const float* __restrict__ kp,
    const int*   __restrict__ idx)
{
    __shared__ __align__(16) __half s_xj[PPB][WARP_XJ];

    const int wid  = threadIdx.x >> 5;
    const int lane = threadIdx.x & 31;
    const int n    = blockIdx.x * PPB + wid;

    __half* xj = &s_xj[wid][0];
    const uint32_t xj_b = smem_u32(xj);

    int idxv = 0;
    if (lane < KNB) idxv = idx[(size_t)n * KNB + lane];

    // ---- issue the x gather as cp.async immediately (prefetch) ----
    #pragma unroll
    for (int i = 0; i < 8; i++) {
        int v   = lane + 32 * i;
        int row = v >> 4;
        int seg = v & 15;
        int j = __shfl_sync(0xFFFFFFFFu, idxv, row);
        cp_async16(xj_b + (uint32_t)row * XJ_ROWB + (uint32_t)seg * 16u,
                   g_x16 + (size_t)j * CIN + 8 * seg, 16u);
    }
    cp_commit();

    // ---- overlapped: pj, max-reduce, corr/expf A-fragment build ----
    const float px = p[3 * n + 0];
    const float py = p[3 * n + 1];
    const float pz = p[3 * n + 2];

    float dx = 0.f, dy = 0.f, dz = 0.f, l2 = 0.f;
    if (lane < KNB) {
        dx = p[3 * idxv + 0] - px;
        dy = p[3 * idxv + 1] - py;
        dz = p[3 * idxv + 2] - pz;
        l2 = sqrtf(dx * dx + dy * dy + dz * dz);
    }
    float mx = l2;
    #pragma unroll
    for (int o = 8; o >= 1; o >>= 1)
        mx = fmaxf(mx, __shfl_xor_sync(0xFFFFFFFFu, mx, o));
    const float inv = 1.0f / (mx + 1e-10f);
    const float pjx = dx * inv, pjy = dy * inv, pjz = dz * inv;

    // pj + zero pad into cols 128..135 (disjoint from cp.async bytes)
    if (lane < KNB) {
        union { uint4 u; __half h[8]; } pk;
        pk.u = make_uint4(0u, 0u, 0u, 0u);
        pk.h[0] = __float2half_rn(pjx);
        pk.h[1] = __float2half_rn(pjy);
        pk.h[2] = __float2half_rn(pjz);
        *(uint4*)(xj + lane * XJ_STRIDE + 128) = pk.u;
    }

    const int q  = lane & 3;
    const int r  = lane >> 2;
    const int k0 = 2 * q;
    const int kl[4] = { k0, k0 + 1, k0 + 8, k0 + 9 };
    float pax[4], pay[4], paz[4];
    #pragma unroll
    for (int i = 0; i < 4; i++) {
        pax[i] = __shfl_sync(0xFFFFFFFFu, pjx, kl[i]);
        pay[i] = __shfl_sync(0xFFFFFFFFu, pjy, kl[i]);
        paz[i] = __shfl_sync(0xFFFFFFFFu, pjz, kl[i]);
    }
    const float INV_SCALE = (float)(1.0 / (0.3 * 0.3 * 2.0 + 1e-10));
    const bool  mhi_ok = (r + 8) < NKP;
    const int   mh = mhi_ok ? (r + 8) : 0;
    const float klx = kp[3 * r + 0], kly = kp[3 * r + 1], klz = kp[3 * r + 2];
    const float khx = kp[3 * mh + 0], khy = kp[3 * mh + 1], khz = kp[3 * mh + 2];

    float clo[4], chi[4];
    #pragma unroll
    for (int i = 0; i < 4; i++) {
        float ax = klx - pax[i], ay = kly - pay[i], az = klz - paz[i];
        clo[i] = __expf(-(ax * ax + ay * ay + az * az) * INV_SCALE);
        float bx = khx - pax[i], by = khy - pay[i], bz = khz - paz[i];
        chi[i] = mhi_ok ? __expf(-(bx * bx + by * by + bz * bz) * INV_SCALE) : 0.f;
    }
    uint32_t afr[4];
    { union { uint32_t u; __half2 h; } t;
      t.h = __floats2half2_rn(clo[0], clo[1]); afr[0] = t.u;
      t.h = __floats2half2_rn(chi[0], chi[1]); afr[1] = t.u;
      t.h = __floats2half2_rn(clo[2], clo[3]); afr[2] = t.u;
      t.h = __floats2half2_rn(chi[2], chi[3]); afr[3] = t.u; }

    // ---- gather must be resident before ldsm ----
    cp_wait<0>();
    __syncwarp();

    float acc[17][4];
    #pragma unroll
    for (int t = 0; t < 17; t++)
        #pragma unroll
        for (int i = 0; i < 4; i++) acc[t][i] = 0.f;

    const uint32_t b_row = xj_b + (uint32_t)(lane & 15) * XJ_ROWB +
                           (uint32_t)(lane >> 4) * 16u;
    #pragma unroll
    for (int nb = 0; nb < 8; nb++) {
        uint32_t t4[4];
        ldsm_x4_t(t4, b_row + (uint32_t)nb * 32u);
        mma_fp16(acc[2 * nb + 0], afr, &t4[0]);
        mma_fp16(acc[2 * nb + 1], afr, &t4[2]);
    }
    {
        uint32_t t2[2];
        ldsm_x2_t(t2, xj_b + (uint32_t)(lane & 15) * XJ_ROWB + 256u);
        mma_fp16(acc[16], afr, t2);
    }
    __syncwarp();

    __half* stg = xj;
    #pragma unroll
    for (int t = 0; t < 17; t++) {
        int c = 8 * t + 2 * q;
        if (t < 16 || q < 2) {
            union { uint32_t u; __half2 h; } v;
            v.h = __floats2half2_rn(acc[t][0], acc[t][1]);
            *(uint32_t*)(stg + r * MROW + c) = v.u;
            if (mhi_ok) {
                v.h = __floats2half2_rn(acc[t][2], acc[t][3]);
                *(uint32_t*)(stg + (r + 8) * MROW + c) = v.u;
            }
        }
    }
    if (lane == 0) *(uint2*)(stg + 1980) = make_uint2(0u, 0u);
    __syncwarp();

    __half* dst = g_agg + (size_t)n * KP2;
    #pragma unroll
    for (int i = lane; i < KP2 / 8; i += 32)
        *(uint4*)(dst + 8 * i) = *(const uint4*)(stg + 8 * i);
}

// ---------------------------------------------------------------------------
// GEMM (R14 verbatim — measured best, at the legacy-HMMA roofline):
// 128x128 tile, 8 warps (64x32 warp tile), 2 CTAs/SM, 3-stage cp.async,
// n on the fast grid axis (L2 A-pairing).
// ---------------------------------------------------------------------------
#define N_TILE   128
#define A_STRIDE 144u
#define B_STRIDE 272u
#define BOFF     18432u
#define STG      35840u
#define NSTAGE   3
#define SMEM_DYN (3u * STG)

__global__ __launch_bounds__(256, 2) void gemm_mma_kernel(
    const float* __restrict__ conv_b,
    const float* __restrict__ bn_gamma,
    const float* __restrict__ bn_beta,
    const float* __restrict__ bn_mean,
    const float* __restrict__ bn_var,
    float* __restrict__ out)
{
    extern __shared__ __align__(1024) char smem[];
    __shared__ __align__(16) float s_sc[N_TILE];
    __shared__ __align__(16) float s_bi[N_TILE];

    const uint32_t sb   = smem_u32(smem);
    const int tid    = threadIdx.x;
    const int wid    = tid >> 5;
    const int lane   = tid & 31;
    const int warp_m = wid >> 2;
    const int warp_n = wid & 3;
    const int m0     = blockIdx.y * 128;      // m slow
    const int n0     = blockIdx.x * N_TILE;   // n fast (L2 pairing)

    if (tid < N_TILE) {
        int col = n0 + tid;
        float s = bn_gamma[col] * rsqrtf(bn_var[col] + 1e-5f);
        s_sc[tid] = s;
        s_bi[tid] = (conv_b[col] - bn_mean[col]) * s + bn_beta[col];
    }

    float acc[4][4][4];
    #pragma unroll
    for (int i = 0; i < 4; i++)
        #pragma unroll
        for (int j = 0; j < 4; j++)
            #pragma unroll
            for (int qq = 0; qq < 4; qq++) acc[i][j][qq] = 0.0f;

    auto load_chunk = [&](int c, int stage) {
        const uint32_t base = sb + (uint32_t)stage * STG;
        #pragma unroll
        for (int L = 0; L < 4; L++) {
            int v   = tid + L * 256;
            int row = v >> 3;
            int seg = v & 7;
            int gr  = m0 + row;
            uint32_t ok = (gr < N_PTS) ? 16u : 0u;
            int grc = (gr < N_PTS) ? gr : 0;
            const __half* src = g_agg + (size_t)grc * KP2 + (size_t)c * 64 + seg * 8;
            uint32_t dst = base + (uint32_t)row * A_STRIDE + (uint32_t)seg * 16u;
            cp_async16(dst, src, ok);
        }
        #pragma unroll
        for (int L = 0; L < 4; L++) {
            int v    = tid + L * 256;
            int krow = v >> 4;
            int seg  = v & 15;
            const __half* src = g_wbt + (size_t)(c * 64 + krow) * COUT + n0 + seg * 8;
            uint32_t dst = base + BOFF +
                           (uint32_t)krow * B_STRIDE + (uint32_t)seg * 16u;
            cp_async16(dst, src, 16u);
        }
        cp_commit();
    };

    const uint32_t a_base = (uint32_t)(warp_m * 64 + (lane & 15)) * A_STRIDE +
                            (uint32_t)(lane >> 4) * 16u;
    const uint32_t b_base = (uint32_t)(lane & 15) * B_STRIDE + BOFF +
                            (uint32_t)(warp_n * 32 + (lane >> 4) * 8) * 2u;

    load_chunk(0, 0);
    load_chunk(1, 1);

    for (int c = 0; c < NCHUNK; c++) {
        if (c + 2 < NCHUNK) load_chunk(c + 2, (c + 2) % NSTAGE);
        else                cp_commit();
        cp_wait<2>();
        __syncthreads();

        const uint32_t stg = sb + (uint32_t)(c % NSTAGE) * STG;

        #pragma unroll
        for (int ks = 0; ks < 4; ks++) {
            uint32_t ah[4][4];
            #pragma unroll
            for (int mi = 0; mi < 4; mi++) {
                uint32_t aa = stg + a_base + (uint32_t)(mi * 16) * A_STRIDE +
                              (uint32_t)ks * 32u;
                ldsm_x4(ah[mi], aa);
            }
            uint32_t bh[4][2];
            #pragma unroll
            for (int nb = 0; nb < 2; nb++) {
                uint32_t ba = stg + b_base + (uint32_t)(ks * 16) * B_STRIDE +
                              (uint32_t)nb * 32u;
                uint32_t t[4];
                ldsm_x4_t(t, ba);
                bh[2*nb][0] = t[0]; bh[2*nb][1] = t[1];
                bh[2*nb+1][0] = t[2]; bh[2*nb+1][1] = t[3];
            }
            #pragma unroll
            for (int mi = 0; mi < 4; mi++)
                #pragma unroll
                for (int ni = 0; ni < 4; ni++)
                    mma_fp16(acc[mi][ni], ah[mi], bh[ni]);
        }
        __syncthreads();
    }

    const int r_base = m0 + warp_m * 64;
    #pragma unroll
    for (int mi = 0; mi < 4; mi++) {
        #pragma unroll
        for (int h = 0; h < 2; h++) {
            int row = r_base + mi * 16 + (lane >> 2) + h * 8;
            if (row < N_PTS) {
                float* op = out + (size_t)row * COUT + n0;
                #pragma unroll
                for (int ni = 0; ni < 4; ni++) {
                    int lc = warp_n * 32 + ni * 8 + (lane & 3) * 2;
                    float2 v;
                    v.x = fmaxf(fmaf(acc[mi][ni][h*2+0], s_sc[lc],   s_bi[lc]),   0.0f);
                    v.y = fmaxf(fmaf(acc[mi][ni][h*2+1], s_sc[lc+1], s_bi[lc+1]), 0.0f);
                    *(float2*)(op + lc) = v;
                }
            }
        }
    }
}

// ---------------------------------------------------------------------------
extern "C" void kernel_launch(void* const* d_in, const int* in_sizes, int n_in,
                              void* d_out, int out_size) {
    const float* p     = (const float*)d_in[0];
    const float* x     = (const float*)d_in[1];
    const float* kp    = (const float*)d_in[2];
    const float* w     = (const float*)d_in[3];
    const float* b     = (const float*)d_in[4];
    const float* gamma = (const float*)d_in[5];
    const float* beta  = (const float*)d_in[6];
    const float* mean  = (const float*)d_in[7];
    const float* var   = (const float*)d_in[8];
    const int*   idx   = (const int*)d_in[9];
    float* out = (float*)d_out;

    cudaFuncSetAttribute(gemm_mma_kernel,
                         cudaFuncAttributeMaxDynamicSharedMemorySize, SMEM_DYN);

    prep_kernel<<<(PREP_UNITS + 255) / 256, 256>>>(x, w);
    preprocess_kernel<<<N_PTS / PPB, 256>>>(p, kp, idx);
    dim3 grid(COUT / N_TILE, (N_PTS + 127) / 128);   // n fast, m slow
    gemm_mma_kernel<<<grid, 256, SMEM_DYN>>>(b, gamma, beta, mean, var, out);
}